// round 17
// baseline (speedup 1.0000x reference)
#include <cuda_runtime.h>

namespace {

constexpr int MAXB = 2048;
constexpr int THREADS = 128;   // 4 warps = 16 groups of 8 lanes; 2 boards per CTA

__device__ __align__(16) float g_W1p[27 * 128];   // W1 transposed: [k][j]
__device__ __align__(16) float g_Wsum[9 * 128];   // W1p[d]+W1p[9+d]+W1p[18+d]
__device__ float4 g_zs[(size_t)MAXB * 81 * 32];   // z scratch: [b][c][j]

__global__ void prep_kernel(const float* __restrict__ W1) {
    int j = threadIdx.x;  // 0..127
    #pragma unroll
    for (int k = 0; k < 27; k++) g_W1p[k * 128 + j] = W1[j * 27 + k];
    #pragma unroll
    for (int d = 0; d < 9; d++)
        g_Wsum[d * 128 + j] = W1[j * 27 + d] + W1[j * 27 + 9 + d] + W1[j * 27 + 18 + d];
}

__device__ __forceinline__ unsigned redux_maxu(unsigned v) {
    unsigned r; asm("redux.sync.max.u32 %0, %1, 0xffffffff;" : "=r"(r) : "r"(v)); return r;
}
__device__ __forceinline__ unsigned redux_minu(unsigned v) {
    unsigned r; asm("redux.sync.min.u32 %0, %1, 0xffffffff;" : "=r"(r) : "r"(v)); return r;
}

__global__ __launch_bounds__(THREADS)
void sudoku_kernel(const float* __restrict__ x,
                   const float* __restrict__ W2,
                   float* __restrict__ out, int B)
{
    __shared__ float4 w2s[288];             // W2 as float4: w2s[e*32+j]
    __shared__ float cnt[2][3][9][9];
    __shared__ float score_s[2][96];        // 81 used; padding reads 0
    __shared__ int   pos_s[2][81];
    __shared__ unsigned char emptyb[2][81];
    __shared__ unsigned char empty0[2][81];

    const int tid  = threadIdx.x;
    const int lane = tid & 31;
    const int grp  = tid >> 3;              // 0..15
    const int gl   = tid & 7;               // owns float4s k*8+gl
    const unsigned gmask = 0xFFu << (lane & 24);
    const int b0 = 2 * blockIdx.x;
    const int nb = (b0 + 1 < B) ? 2 : 1;

    for (int i = tid; i < 288; i += THREADS) w2s[i] = ((const float4*)W2)[i];

    auto reduce8 = [&](float4 z4[4], float p[9]) {
        #pragma unroll
        for (int k = 0; k < 4; k++) {
            z4[k].x = fmaxf(z4[k].x, 0.f); z4[k].y = fmaxf(z4[k].y, 0.f);
            z4[k].z = fmaxf(z4[k].z, 0.f); z4[k].w = fmaxf(z4[k].w, 0.f);
        }
        #pragma unroll
        for (int e = 0; e < 9; e++) {
            float a = 0.f;
            #pragma unroll
            for (int k = 0; k < 4; k++) {
                float4 w = w2s[e * 32 + k * 8 + gl];
                a = fmaf(z4[k].x, w.x, a); a = fmaf(z4[k].y, w.y, a);
                a = fmaf(z4[k].z, w.z, a); a = fmaf(z4[k].w, w.w, a);
            }
            p[e] = a;
        }
        #pragma unroll
        for (int off = 4; off > 0; off >>= 1) {
            #pragma unroll
            for (int e = 0; e < 9; e++)
                p[e] += __shfl_xor_sync(gmask, p[e], off);
        }
    };

    auto scorepos8 = [&](int bs, int c, const float p[9]) {
        float mx = p[0];
        #pragma unroll
        for (int e = 1; e < 9; e++) mx = fmaxf(mx, p[e]);
        float sum = 0.f, best = -1.f; int bp = 0;
        #pragma unroll
        for (int e = 0; e < 9; e++) {
            float q = __expf(p[e] - mx);
            sum += q;
            if (q > best) { best = q; bp = e; }   // strict > = first max
        }
        if (gl == 0) { score_s[bs][c] = __fdividef(best, sum); pos_s[bs][c] = bp; }
    };

    auto map_cell = [](int i, int rm, int cm3, int brm) -> int {
        if (i < 3)  return 3 * rm + i;
        if (i < 12) return 27 + 3 * (i - 3) + cm3;
        return 54 + 3 * (brm + (i - 12)) + cm3;
    };

    // ---- per-board init ----
    for (int bs = 0; bs < nb; bs++) {
        const float* xb = x + (long long)(b0 + bs) * 729;
        float* ob = out + (long long)(b0 + bs) * 729;
        for (int i = tid; i < 243; i += THREADS) (&cnt[bs][0][0][0])[i] = 0.f;
        for (int i = tid; i < 729; i += THREADS) ob[i] = xb[i];
        if (tid < 96) score_s[bs][tid] = 0.f;
        __syncthreads();
        if (tid < 81) {
            int d = -1;
            #pragma unroll
            for (int e = 0; e < 9; e++)
                if (xb[tid * 9 + e] > 0.5f) d = e;
            pos_s[bs][tid] = 0;
            if (d >= 0) {
                emptyb[bs][tid] = 0; empty0[bs][tid] = 0;
                int r = tid / 9, cc = tid % 9, bx = (r / 3) * 3 + cc / 3;
                atomicAdd(&cnt[bs][0][r][d],  1.f);
                atomicAdd(&cnt[bs][1][cc][d], 1.f);
                atomicAdd(&cnt[bs][2][bx][d], 1.f);
            } else {
                emptyb[bs][tid] = 1; empty0[bs][tid] = 1;
            }
        }
        __syncthreads();
    }

    // ---- Initial pass: fresh z for every empty cell of both boards ----
    for (int bs = 0; bs < nb; bs++) {
        float4* zb = g_zs + (size_t)(b0 + bs) * 81 * 32;
        for (int base = 0; base < 27; base += 16) {
            int cc = base + grp;
            if (cc < 27 && emptyb[bs][cc]) {
                const float* f = cnt[bs][0][cc / 3];
                float4 z4[4] = {};
                #pragma unroll
                for (int e = 0; e < 9; e++) {
                    float fv = f[e];
                    #pragma unroll
                    for (int k = 0; k < 4; k++) {
                        float4 w = __ldg((const float4*)(g_Wsum + e * 128) + k * 8 + gl);
                        z4[k].x = fmaf(fv, w.x, z4[k].x); z4[k].y = fmaf(fv, w.y, z4[k].y);
                        z4[k].z = fmaf(fv, w.z, z4[k].z); z4[k].w = fmaf(fv, w.w, z4[k].w);
                    }
                }
                #pragma unroll
                for (int k = 0; k < 4; k++) zb[cc * 32 + k * 8 + gl] = z4[k];
                float p[9]; reduce8(z4, p);
                scorepos8(bs, cc, p);
            }
        }
        for (int base = 0; base < 27; base += 16) {
            int cc = base + grp;
            if (cc < 27 && emptyb[bs][cc + 27]) {
                int g0 = 3 * (cc % 3);
                float4 z4[4] = {};
                #pragma unroll
                for (int blk = 0; blk < 3; blk++) {
                    const float* f = cnt[bs][1][g0 + blk];
                    #pragma unroll
                    for (int e = 0; e < 9; e++) {
                        float fv = f[e];
                        #pragma unroll
                        for (int k = 0; k < 4; k++) {
                            float4 w = __ldg((const float4*)(g_W1p + (9 * blk + e) * 128) + k * 8 + gl);
                            z4[k].x = fmaf(fv, w.x, z4[k].x); z4[k].y = fmaf(fv, w.y, z4[k].y);
                            z4[k].z = fmaf(fv, w.z, z4[k].z); z4[k].w = fmaf(fv, w.w, z4[k].w);
                        }
                    }
                }
                int co = cc + 27;
                #pragma unroll
                for (int k = 0; k < 4; k++) zb[co * 32 + k * 8 + gl] = z4[k];
                float p[9]; reduce8(z4, p);
                scorepos8(bs, co, p);
            }
        }
        for (int base = 0; base < 27; base += 16) {
            int cc = base + grp;
            if (cc < 27 && emptyb[bs][cc + 54]) {
                const float* f = cnt[bs][2][3 * (cc / 9) + cc % 3];
                float4 z4[4] = {};
                #pragma unroll
                for (int e = 0; e < 9; e++) {
                    float fv = f[e];
                    #pragma unroll
                    for (int k = 0; k < 4; k++) {
                        float4 w = __ldg((const float4*)(g_Wsum + e * 128) + k * 8 + gl);
                        z4[k].x = fmaf(fv, w.x, z4[k].x); z4[k].y = fmaf(fv, w.y, z4[k].y);
                        z4[k].z = fmaf(fv, w.z, z4[k].z); z4[k].w = fmaf(fv, w.w, z4[k].w);
                    }
                }
                int co = cc + 54;
                #pragma unroll
                for (int k = 0; k < 4; k++) zb[co * 32 + k * 8 + gl] = z4[k];
                float p[9]; reduce8(z4, p);
                scorepos8(bs, co, p);
            }
        }
    }
    __syncthreads();

    // ---- Sequential fill loop: ONE barrier per iteration for BOTH boards ----
    // Race-free: fills-register masking per board, no score smem clear.
    unsigned fills0 = 0, fills1 = 0;
    bool done0 = false, done1 = (nb < 2);
    for (int iter = 0; iter < 81 && !(done0 && done1); ++iter) {
        int m0 = -1, d0 = 0, ne0 = 0; unsigned mask0 = 0;
        int rm0 = 0, cm0 = 0, cm30 = 0, brm0 = 0;
        if (!done0) {
            float s0 = (fills0 & 1u) ? 0.f : score_s[0][lane];
            float s1 = (fills0 & 2u) ? 0.f : score_s[0][lane + 32];
            float s2 = (fills0 & 4u) ? 0.f : score_s[0][lane + 64];
            unsigned bb = __float_as_uint(s0); int bi = lane;
            unsigned v1 = __float_as_uint(s1); if (v1 > bb) { bb = v1; bi = lane + 32; }
            unsigned v2 = __float_as_uint(s2); if (v2 > bb) { bb = v2; bi = lane + 64; }
            unsigned wmax = redux_maxu(bb);
            if (wmax == 0u) done0 = true;
            else {
                unsigned cand = (bb == wmax) ? (unsigned)bi : 0xFFu;
                m0 = (int)redux_minu(cand);
                d0 = pos_s[0][m0];
                if (m0 == lane)      fills0 |= 1u;
                if (m0 == lane + 32) fills0 |= 2u;
                if (m0 == lane + 64) fills0 |= 4u;
                rm0 = m0 / 9; cm0 = m0 % 9; cm30 = cm0 / 3; brm0 = (rm0 / 3) * 3;
                int cl = map_cell(lane < 15 ? lane : 0, rm0, cm30, brm0);
                bool pr = (lane < 15) && (cl != m0) && emptyb[0][cl];
                mask0 = __ballot_sync(0xffffffffu, pr);
                ne0 = __popc(mask0);
            }
        }
        int m1 = -1, d1 = 0, ne1 = 0; unsigned mask1 = 0;
        int rm1 = 0, cm1 = 0, cm31 = 0, brm1 = 0;
        if (!done1) {
            float s0 = (fills1 & 1u) ? 0.f : score_s[1][lane];
            float s1 = (fills1 & 2u) ? 0.f : score_s[1][lane + 32];
            float s2 = (fills1 & 4u) ? 0.f : score_s[1][lane + 64];
            unsigned bb = __float_as_uint(s0); int bi = lane;
            unsigned v1 = __float_as_uint(s1); if (v1 > bb) { bb = v1; bi = lane + 32; }
            unsigned v2 = __float_as_uint(s2); if (v2 > bb) { bb = v2; bi = lane + 64; }
            unsigned wmax = redux_maxu(bb);
            if (wmax == 0u) done1 = true;
            else {
                unsigned cand = (bb == wmax) ? (unsigned)bi : 0xFFu;
                m1 = (int)redux_minu(cand);
                d1 = pos_s[1][m1];
                if (m1 == lane)      fills1 |= 1u;
                if (m1 == lane + 32) fills1 |= 2u;
                if (m1 == lane + 64) fills1 |= 4u;
                rm1 = m1 / 9; cm1 = m1 % 9; cm31 = cm1 / 3; brm1 = (rm1 / 3) * 3;
                int cl = map_cell(lane < 15 ? lane : 0, rm1, cm31, brm1);
                bool pr = (lane < 15) && (cl != m1) && emptyb[1][cl];
                mask1 = __ballot_sync(0xffffffffu, pr);
                ne1 = __popc(mask1);
            }
        }

        if (tid == 0) {
            if (m0 >= 0) emptyb[0][m0] = 0;   // read only after next barrier
            if (m1 >= 0) emptyb[1][m1] = 0;
        }

        // group work: concatenated cell list [0, ne0) board0, [ne0, ne0+ne1) board1
        int total = ne0 + ne1;                 // <= 28 -> at most 2 passes
        for (int idx = grp; idx < total; idx += 16) {
            int bs, bit, c; const float* wrow;
            if (idx < ne0) {
                bs = 0;
                bit = (int)__fns(mask0, 0, idx + 1);
                c = map_cell(bit, rm0, cm30, brm0);
                wrow = (bit >= 3 && bit < 12) ? g_W1p + (9 * (cm0 % 3) + d0) * 128
                                              : g_Wsum + d0 * 128;
            } else {
                bs = 1;
                bit = (int)__fns(mask1, 0, idx - ne0 + 1);
                c = map_cell(bit, rm1, cm31, brm1);
                wrow = (bit >= 3 && bit < 12) ? g_W1p + (9 * (cm1 % 3) + d1) * 128
                                              : g_Wsum + d1 * 128;
            }
            float4* zb = g_zs + (size_t)(b0 + bs) * 81 * 32;
            float4 z4[4];
            #pragma unroll
            for (int k = 0; k < 4; k++) {
                float4 z = zb[c * 32 + k * 8 + gl];
                float4 w = __ldg((const float4*)wrow + k * 8 + gl);
                z.x += w.x; z.y += w.y; z.z += w.z; z.w += w.w;
                z4[k] = z;
            }
            #pragma unroll
            for (int k = 0; k < 4; k++) zb[c * 32 + k * 8 + gl] = z4[k];
            float p[9]; reduce8(z4, p);
            scorepos8(bs, c, p);
        }

        __syncthreads();   // publish z/score/pos + emptyb clears for both boards
    }
    __syncthreads();

    // ---- Final pass: softmax of frozen z for initially-empty cells ----
    for (int bs = 0; bs < nb; bs++) {
        float4* zb = g_zs + (size_t)(b0 + bs) * 81 * 32;
        float* ob = out + (long long)(b0 + bs) * 729;
        for (int base = 0; base < 81; base += 16) {
            int c = base + grp;
            if (c < 81 && empty0[bs][c]) {
                float4 z4[4];
                #pragma unroll
                for (int k = 0; k < 4; k++) z4[k] = zb[c * 32 + k * 8 + gl];
                float p[9]; reduce8(z4, p);
                float mx = p[0];
                #pragma unroll
                for (int e = 1; e < 9; e++) mx = fmaxf(mx, p[e]);
                float sum = 0.f;
                #pragma unroll
                for (int e = 0; e < 9; e++) { p[e] = __expf(p[e] - mx); sum += p[e]; }
                ob[c * 9 + gl] = __fdividef(p[gl], sum);
                if (gl == 0) ob[c * 9 + 8] = __fdividef(p[8], sum);
            }
        }
    }
}

} // namespace

extern "C" void kernel_launch(void* const* d_in, const int* in_sizes, int n_in,
                              void* d_out, int out_size) {
    const float* x  = (const float*)d_in[0];
    const float* W1 = (const float*)d_in[1];
    const float* W2 = (const float*)d_in[2];
    float* out = (float*)d_out;
    int B = in_sizes[0] / 729;
    prep_kernel<<<1, 128>>>(W1);
    sudoku_kernel<<<(B + 1) / 2, THREADS>>>(x, W2, out, B);
}